// round 4
// baseline (speedup 1.0000x reference)
#include <cuda_runtime.h>

#define BATCH 256
#define SEQ   2048
#define EMBD  16
#define HIDD  32
#define GATE  128

// 256 MB scratch: pre-activation input projection z = emb[tok]@Wk + b, [b*t][128]
__device__ float g_zx[(size_t)BATCH * SEQ * GATE];

__device__ __forceinline__ float tanha(float x){
    float y; asm("tanh.approx.f32 %0, %1;" : "=f"(y) : "f"(x)); return y;
}

// ─────────────── Phase 1: zx = emb[tok]@Wk + b (streaming, DRAM-bound) ──────
// Thread owns column (tid&127); 128-thread groups sweep tokens grid-stride.
__global__ __launch_bounds__(512) void proj_kernel(
    const int*   __restrict__ tokens,
    const float* __restrict__ emb,
    const float* __restrict__ Wk,
    const float* __restrict__ bias)
{
    const int col    = threadIdx.x & 127;
    const int group  = blockIdx.x * 4 + (threadIdx.x >> 7);
    const int stride = gridDim.x * 4;

    float wk[EMBD];
    #pragma unroll
    for (int e = 0; e < EMBD; e++) wk[e] = Wk[e*GATE + col];
    const float bz = bias[col];

    const int total = BATCH * SEQ;
    for (int s = group; s < total; s += 2*stride){
        const int s1 = s + stride;
        const int tokA = tokens[s];
        const int tokB = (s1 < total) ? tokens[s1] : 0;
        const float* xa = emb + tokA * EMBD;
        const float* xb = emb + tokB * EMBD;
        float za = bz, zb = bz;
        #pragma unroll
        for (int e = 0; e < EMBD; e++){
            za = fmaf(xa[e], wk[e], za);
            zb = fmaf(xb[e], wk[e], zb);
        }
        g_zx[(size_t)s  * GATE + col] = za;
        if (s1 < total) g_zx[(size_t)s1 * GATE + col] = zb;
    }
}

// ─────────────── Phase 2: masked LSTM recurrence ────────────────────────────
// 4 warps/sequence. Lane l = (gate q=l>>3, hid jj=l&7); warp w owns hid
// [8w,8w+8) for all 4 gates. h broadcast via smem LDS.128; gate combine via
// 3 shfl_xor (depth 2), replicated; one __syncthreads/step; branch-free body.
__global__ __launch_bounds__(128) void rec_kernel(
    const int*   __restrict__ tokens,
    const float* __restrict__ Wr,
    float*       __restrict__ out)
{
    __shared__ float h2[2][HIDD];

    const int b   = blockIdx.x;
    const int tid = threadIdx.x;
    const int w   = tid >> 5;
    const int l   = tid & 31;
    const int q   = l >> 3;          // gate: 0=i 1=f 2=g 3=o
    const int jj  = l & 7;
    const int hid = (w << 3) + jj;
    const int col = (q << 5) + hid;

    float wr[HIDD];
    #pragma unroll
    for (int k = 0; k < HIDD; k++) wr[k] = Wr[k*GATE + col];

    // activation folding: a = off + s*tanh(s*z)  (s=1 -> tanh, s=0.5 -> sigmoid)
    const float s_act = (q == 2) ? 1.0f : 0.5f;
    const float o_act = (q == 2) ? 0.0f : 0.5f;

    const float* __restrict__ zp   = g_zx + (size_t)b * SEQ * GATE + col;
    const int*   __restrict__ tptr = tokens + b * SEQ;
    float* optr = out + (size_t)b * SEQ * HIDD + hid;

    if (tid < HIDD) h2[0][tid] = 0.0f;

    float rz[4]; int rtok[4];
    #pragma unroll
    for (int p = 0; p < 3; p++){
        rz[p]   = zp[(size_t)p * GATE];
        rtok[p] = tptr[p];
    }
    __syncthreads();

    float h = 0.0f, c = 0.0f;

    #pragma unroll 2
    for (int t = 0; t < SEQ; t++){
        const int rb = t & 1, wb = rb ^ 1;

        // branch-free prefetch, 3 steps ahead (clamped)
        const int pidx = min(t + 3, SEQ - 1);
        rz[(t + 3) & 3]   = zp[(size_t)pidx * GATE];
        rtok[(t + 3) & 3] = tptr[pidx];

        const float zx  = rz[t & 3];
        const int   tok = rtok[t & 3];

        // matvec: z_col(t) = zx + sum_k h(t-1)_k * Wr[k][col]
        const float4* hb = (const float4*)h2[rb];
        float s0 = 0.f, s1 = 0.f, s2 = 0.f, s3 = 0.f;
        {
            float4 x0 = hb[0], x1 = hb[1];
            s0 = fmaf(x0.x, wr[0], s0);  s0 = fmaf(x0.y, wr[1], s0);
            s0 = fmaf(x0.z, wr[2], s0);  s0 = fmaf(x0.w, wr[3], s0);
            s0 = fmaf(x1.x, wr[4], s0);  s0 = fmaf(x1.y, wr[5], s0);
            s0 = fmaf(x1.z, wr[6], s0);  s0 = fmaf(x1.w, wr[7], s0);
        }
        {
            float4 x0 = hb[2], x1 = hb[3];
            s1 = fmaf(x0.x, wr[8],  s1); s1 = fmaf(x0.y, wr[9],  s1);
            s1 = fmaf(x0.z, wr[10], s1); s1 = fmaf(x0.w, wr[11], s1);
            s1 = fmaf(x1.x, wr[12], s1); s1 = fmaf(x1.y, wr[13], s1);
            s1 = fmaf(x1.z, wr[14], s1); s1 = fmaf(x1.w, wr[15], s1);
        }
        {
            float4 x0 = hb[4], x1 = hb[5];
            s2 = fmaf(x0.x, wr[16], s2); s2 = fmaf(x0.y, wr[17], s2);
            s2 = fmaf(x0.z, wr[18], s2); s2 = fmaf(x0.w, wr[19], s2);
            s2 = fmaf(x1.x, wr[20], s2); s2 = fmaf(x1.y, wr[21], s2);
            s2 = fmaf(x1.z, wr[22], s2); s2 = fmaf(x1.w, wr[23], s2);
        }
        {
            float4 x0 = hb[6], x1 = hb[7];
            s3 = fmaf(x0.x, wr[24], s3); s3 = fmaf(x0.y, wr[25], s3);
            s3 = fmaf(x0.z, wr[26], s3); s3 = fmaf(x0.w, wr[27], s3);
            s3 = fmaf(x1.x, wr[28], s3); s3 = fmaf(x1.y, wr[29], s3);
            s3 = fmaf(x1.z, wr[30], s3); s3 = fmaf(x1.w, wr[31], s3);
        }
        const float z = zx + ((s0 + s1) + (s2 + s3));

        // activate (one MUFU), exchange gates intra-warp (3 shfl, depth 2)
        const float a   = fmaf(s_act, tanha(s_act * z), o_act);
        const float v8  = __shfl_xor_sync(0xffffffffu, a,  8);
        const float v16 = __shfl_xor_sync(0xffffffffu, a, 16);
        const float v24 = __shfl_xor_sync(0xffffffffu, v8, 16);

        // gate g' lives at distance d = q ^ g'
        const float gi = (q == 0) ? a : (q == 1) ? v8 : (q == 2) ? v16 : v24;
        const float gf = (q == 1) ? a : (q == 0) ? v8 : (q == 3) ? v16 : v24;
        const float gg = (q == 2) ? a : (q == 3) ? v8 : (q == 0) ? v16 : v24;
        const float go = (q == 3) ? a : (q == 2) ? v8 : (q == 1) ? v16 : v24;

        const float cn = fmaf(gf, c, gi * gg);
        const float hn = go * tanha(cn);
        const bool  m  = (tok != 0);
        c = m ? cn : c;
        h = m ? hn : h;

        h2[wb][hid] = h;                      // 4 lanes, same addr, same value
        if (q == 0) optr[(size_t)t * HIDD] = h;  // predicated STG, 8/warp

        __syncthreads();
    }
}

extern "C" void kernel_launch(void* const* d_in, const int* in_sizes, int n_in,
                              void* d_out, int out_size)
{
    (void)in_sizes; (void)n_in; (void)out_size;
    const int*   tokens = (const int*)  d_in[0];
    const float* emb    = (const float*)d_in[1];
    const float* Wk     = (const float*)d_in[2];
    const float* Wr     = (const float*)d_in[3];
    const float* bias   = (const float*)d_in[4];
    float* out = (float*)d_out;

    proj_kernel<<<1024, 512>>>(tokens, emb, Wk, bias);
    rec_kernel<<<BATCH, 128>>>(tokens, Wr, out);
}

// round 5
// speedup vs baseline: 1.6245x; 1.6245x over previous
#include <cuda_runtime.h>

#define BATCH 256
#define SEQ   2048
#define EMBD  16
#define HIDD  32
#define GATE  128

// 256 MB scratch: pre-activation input projection z = emb[tok]@Wk + b, [b*t][128]
__device__ float g_zx[(size_t)BATCH * SEQ * GATE];

__device__ __forceinline__ float tanha(float x){
    float y; asm("tanh.approx.f32 %0, %1;" : "=f"(y) : "f"(x)); return y;
}

// ─────────────── Phase 1: zx = emb[tok]@Wk + b (streaming, DRAM-bound) ──────
__global__ __launch_bounds__(512) void proj_kernel(
    const int*   __restrict__ tokens,
    const float* __restrict__ emb,
    const float* __restrict__ Wk,
    const float* __restrict__ bias)
{
    const int col    = threadIdx.x & 127;
    const int group  = blockIdx.x * 4 + (threadIdx.x >> 7);
    const int stride = gridDim.x * 4;

    float wk[EMBD];
    #pragma unroll
    for (int e = 0; e < EMBD; e++) wk[e] = Wk[e*GATE + col];
    const float bz = bias[col];

    const int total = BATCH * SEQ;
    for (int s = group; s < total; s += 2*stride){
        const int s1 = s + stride;
        const int tokA = tokens[s];
        const int tokB = (s1 < total) ? tokens[s1] : 0;
        const float* xa = emb + tokA * EMBD;
        const float* xb = emb + tokB * EMBD;
        float za = bz, zb = bz;
        #pragma unroll
        for (int e = 0; e < EMBD; e++){
            za = fmaf(xa[e], wk[e], za);
            zb = fmaf(xb[e], wk[e], zb);
        }
        g_zx[(size_t)s  * GATE + col] = za;
        if (s1 < total) g_zx[(size_t)s1 * GATE + col] = zb;
    }
}

// ─────────────── Phase 2: masked LSTM recurrence ────────────────────────────
// 4 warps/sequence. Lane l = (gate q=l>>3, hid jj=l&7); warp w owns hid
// [8w,8w+8) for all 4 gates (32 FMA/lane/step). h broadcast via smem LDS.128;
// gate exchange via 3 INDEPENDENT shfl.bfly; one __syncthreads/step.
// Loop unrolled 4x so the &3 register rings resolve at compile time (the R3/R4
// regression was these rings spilling to local memory).
__global__ __launch_bounds__(128) void rec_kernel(
    const int*   __restrict__ tokens,
    const float* __restrict__ Wr,
    float*       __restrict__ out)
{
    __shared__ float h2[2][HIDD];

    const int b   = blockIdx.x;
    const int tid = threadIdx.x;
    const int w   = tid >> 5;
    const int l   = tid & 31;
    const int q   = l >> 3;          // gate: 0=i 1=f 2=g 3=o
    const int jj  = l & 7;
    const int hid = (w << 3) + jj;
    const int col = (q << 5) + hid;

    float wr[HIDD];
    #pragma unroll
    for (int k = 0; k < HIDD; k++) wr[k] = Wr[k*GATE + col];

    // activation folding: a = off + s*tanh(s*z)  (s=1 -> tanh, s=0.5 -> sigmoid)
    const float s_act = (q == 2) ? 1.0f : 0.5f;
    const float o_act = (q == 2) ? 0.0f : 0.5f;

    const float* __restrict__ zp   = g_zx + (size_t)b * SEQ * GATE + col;
    const int*   __restrict__ tptr = tokens + b * SEQ;
    float* optr = out + (size_t)b * SEQ * HIDD + hid;

    if (tid < HIDD) h2[0][tid] = 0.0f;

    float rz[4]; int rtok[4];
    #pragma unroll
    for (int p = 0; p < 3; p++){
        rz[p]   = zp[(size_t)p * GATE];
        rtok[p] = tptr[p];
    }
    __syncthreads();

    float h = 0.0f, c = 0.0f;

    #pragma unroll 4
    for (int t = 0; t < SEQ; t++){
        const int rb = t & 1, wb = rb ^ 1;

        // Issue prefetch (t+3, clamped) BEFORE the barrier so LDG latency
        // overlaps bar release. Indices (t+3)&3 are compile-time under unroll 4.
        const int pidx = min(t + 3, SEQ - 1);
        rz[(t + 3) & 3]   = zp[(size_t)pidx * GATE];
        rtok[(t + 3) & 3] = tptr[pidx];

        __syncthreads();   // h2[rb] from step t-1 now visible

        const float zx  = rz[t & 3];
        const int   tok = rtok[t & 3];

        // matvec: z_col(t) = zx + sum_k h(t-1)_k * Wr[k][col]
        // 4 independent 8-deep FMA chains fed by broadcast LDS.128.
        const float4* hb = (const float4*)h2[rb];
        float s0, s1, s2, s3;
        {
            float4 x0 = hb[0], x1 = hb[1];
            s0 = fmaf(x0.x, wr[0], 0.0f); s0 = fmaf(x0.y, wr[1], s0);
            s0 = fmaf(x0.z, wr[2], s0);   s0 = fmaf(x0.w, wr[3], s0);
            s0 = fmaf(x1.x, wr[4], s0);   s0 = fmaf(x1.y, wr[5], s0);
            s0 = fmaf(x1.z, wr[6], s0);   s0 = fmaf(x1.w, wr[7], s0);
        }
        {
            float4 x0 = hb[2], x1 = hb[3];
            s1 = fmaf(x0.x, wr[8],  0.0f); s1 = fmaf(x0.y, wr[9],  s1);
            s1 = fmaf(x0.z, wr[10], s1);   s1 = fmaf(x0.w, wr[11], s1);
            s1 = fmaf(x1.x, wr[12], s1);   s1 = fmaf(x1.y, wr[13], s1);
            s1 = fmaf(x1.z, wr[14], s1);   s1 = fmaf(x1.w, wr[15], s1);
        }
        {
            float4 x0 = hb[4], x1 = hb[5];
            s2 = fmaf(x0.x, wr[16], 0.0f); s2 = fmaf(x0.y, wr[17], s2);
            s2 = fmaf(x0.z, wr[18], s2);   s2 = fmaf(x0.w, wr[19], s2);
            s2 = fmaf(x1.x, wr[20], s2);   s2 = fmaf(x1.y, wr[21], s2);
            s2 = fmaf(x1.z, wr[22], s2);   s2 = fmaf(x1.w, wr[23], s2);
        }
        {
            float4 x0 = hb[6], x1 = hb[7];
            s3 = fmaf(x0.x, wr[24], 0.0f); s3 = fmaf(x0.y, wr[25], s3);
            s3 = fmaf(x0.z, wr[26], s3);   s3 = fmaf(x0.w, wr[27], s3);
            s3 = fmaf(x1.x, wr[28], s3);   s3 = fmaf(x1.y, wr[29], s3);
            s3 = fmaf(x1.z, wr[30], s3);   s3 = fmaf(x1.w, wr[31], s3);
        }
        const float z = (zx + s0) + ((s1 + s2) + s3);

        // activate (one MUFU), exchange gates: 3 independent butterflies
        const float a   = fmaf(s_act, tanha(s_act * z), o_act);
        const float v8  = __shfl_xor_sync(0xffffffffu, a,  8);
        const float v16 = __shfl_xor_sync(0xffffffffu, a, 16);
        const float v24 = __shfl_xor_sync(0xffffffffu, a, 24);

        // gate g' sits at xor-distance d = q ^ g'
        const float gi = (q == 0) ? a : (q == 1) ? v8 : (q == 2) ? v16 : v24;
        const float gf = (q == 1) ? a : (q == 0) ? v8 : (q == 3) ? v16 : v24;
        const float gg = (q == 2) ? a : (q == 3) ? v8 : (q == 0) ? v16 : v24;
        const float go = (q == 3) ? a : (q == 2) ? v8 : (q == 1) ? v16 : v24;

        const float cn = fmaf(gf, c, gi * gg);
        const float hn = go * tanha(cn);
        const bool  m  = (tok != 0);
        c = m ? cn : c;
        h = m ? hn : h;

        if (q == 0){
            h2[wb][hid] = h;                 // 8 lanes/warp, conflict-free
            optr[(size_t)t * HIDD] = h;      // 32B STG per warp
        }
    }
}

extern "C" void kernel_launch(void* const* d_in, const int* in_sizes, int n_in,
                              void* d_out, int out_size)
{
    (void)in_sizes; (void)n_in; (void)out_size;
    const int*   tokens = (const int*)  d_in[0];
    const float* emb    = (const float*)d_in[1];
    const float* Wk     = (const float*)d_in[2];
    const float* Wr     = (const float*)d_in[3];
    const float* bias   = (const float*)d_in[4];
    float* out = (float*)d_out;

    proj_kernel<<<1024, 512>>>(tokens, emb, Wk, bias);
    rec_kernel<<<BATCH, 128>>>(tokens, Wr, out);
}

// round 6
// speedup vs baseline: 1.8057x; 1.1115x over previous
#include <cuda_runtime.h>

#define BATCH 256
#define SEQ   2048
#define EMBD  16
#define HIDD  32
#define GATE  128

typedef unsigned long long u64;

// 256 MB scratch: gate-packed input projection, float4(i,f,g,o) per (token, hid)
__device__ float4 g_zx[(size_t)BATCH * SEQ * HIDD];

__device__ __forceinline__ u64 pack2(float lo, float hi){
    u64 r; asm("mov.b64 %0, {%1,%2};" : "=l"(r) : "f"(lo), "f"(hi)); return r;
}
__device__ __forceinline__ void unpack2(u64 v, float& lo, float& hi){
    asm("mov.b64 {%0,%1}, %2;" : "=f"(lo), "=f"(hi) : "l"(v));
}
__device__ __forceinline__ u64 ffma2(u64 a, u64 b, u64 c){
    u64 d; asm("fma.rn.f32x2 %0, %1, %2, %3;" : "=l"(d) : "l"(a), "l"(b), "l"(c)); return d;
}
__device__ __forceinline__ float tanha(float x){
    float y; asm("tanh.approx.f32 %0, %1;" : "=f"(y) : "f"(x)); return y;
}
// sigmoid(z) = 0.5 + 0.5*tanh(z/2)
__device__ __forceinline__ float sigt(float z){
    return fmaf(0.5f, tanha(0.5f * z), 0.5f);
}

// ─────────────── Phase 1: zx = emb[tok]@Wk + b  (R2-proven, DRAM-bound) ─────
__global__ __launch_bounds__(256) void proj_kernel(
    const int*   __restrict__ tokens,
    const float* __restrict__ emb,
    const float* __restrict__ Wk,
    const float* __restrict__ bias)
{
    const int j    = threadIdx.x & 31;
    const int warp = (blockIdx.x << 3) + (threadIdx.x >> 5);
    const int base = warp << 8;                  // 256 tokens per warp

    u64 wk_if[EMBD], wk_go[EMBD];
    #pragma unroll
    for (int e = 0; e < EMBD; e++){
        wk_if[e] = pack2(Wk[e*GATE + j],      Wk[e*GATE + j + 32]);
        wk_go[e] = pack2(Wk[e*GATE + j + 64], Wk[e*GATE + j + 96]);
    }
    const u64 b_if = pack2(bias[j],      bias[j + 32]);
    const u64 b_go = pack2(bias[j + 64], bias[j + 96]);

    for (int s = 0; s < 256; s += 2){
        const int tflat = base + s + (j >> 4);   // lanes 0-15: s, 16-31: s+1
        const int tok   = tokens[tflat];
        const float xv  = emb[tok * EMBD + (j & 15)];

        u64 aI = b_if, aG = b_go;                // token A
        u64 cI = b_if, cG = b_go;                // token B
        #pragma unroll
        for (int e = 0; e < EMBD; e++){
            float xa = __shfl_sync(0xffffffffu, xv, e);
            float xb = __shfl_sync(0xffffffffu, xv, 16 + e);
            u64 xa2 = pack2(xa, xa);
            u64 xb2 = pack2(xb, xb);
            aI = ffma2(xa2, wk_if[e], aI);
            aG = ffma2(xa2, wk_go[e], aG);
            cI = ffma2(xb2, wk_if[e], cI);
            cG = ffma2(xb2, wk_go[e], cG);
        }
        float4 zA, zB;
        unpack2(aI, zA.x, zA.y); unpack2(aG, zA.z, zA.w);
        unpack2(cI, zB.x, zB.y); unpack2(cG, zB.z, zB.w);
        g_zx[(size_t)(base + s)     * HIDD + j] = zA;
        g_zx[(size_t)(base + s + 1) * HIDD + j] = zB;
    }
}

// ─────────────── Phase 2: barrier-free single-warp recurrence ───────────────
// One warp per sequence. Lane j owns hid j + gate columns (j,j+32,j+64,j+96).
// h broadcast purely via shfl.idx (alu pipe, overlaps fma pipe); no smem, no
// barriers, no divergent branches. 128 scalar FFMA/step (fma-pipe floor 256cy)
// as 8 split chains; 5 MUFU.TANH pipelined into the FMA tail.
__global__ __launch_bounds__(32) void rec_kernel(
    const int*   __restrict__ tokens,
    const float* __restrict__ Wr,
    float*       __restrict__ out)
{
    const int b = blockIdx.x;
    const int j = threadIdx.x;

    // 128 weight registers: wr_<gate>[k] = Wr[k][gatecol]
    float wi[HIDD], wf[HIDD], wg[HIDD], wo[HIDD];
    #pragma unroll
    for (int k = 0; k < HIDD; k++){
        wi[k] = Wr[k*GATE + j];
        wf[k] = Wr[k*GATE + j + 32];
        wg[k] = Wr[k*GATE + j + 64];
        wo[k] = Wr[k*GATE + j + 96];
    }

    const float4* __restrict__ zp   = g_zx + (size_t)b * SEQ * HIDD + j;
    const int*    __restrict__ tptr = tokens + b * SEQ;
    float* optr = out + (size_t)b * SEQ * HIDD + j;

    float4 rz[4]; int rtok[4];
    #pragma unroll
    for (int p = 0; p < 3; p++){
        rz[p]   = zp[(size_t)p * HIDD];
        rtok[p] = tptr[p];
    }

    float h = 0.0f, c = 0.0f;

    #pragma unroll 4
    for (int t = 0; t < SEQ; t++){
        // prefetch t+3 (clamped, branch-free; ring indices compile-time)
        const int pidx = min(t + 3, SEQ - 1);
        rz[(t + 3) & 3]   = zp[(size_t)pidx * HIDD];
        rtok[(t + 3) & 3] = tptr[pidx];

        const float4 z4  = rz[t & 3];
        const int    tok = rtok[t & 3];

        // z = zx + Wr^T h : 8 split chains (2 per gate), shfl-broadcast h
        float i0, i1, f0, f1, g0, g1, o0, o1;
        {
            const float hk = __shfl_sync(0xffffffffu, h, 0);
            i0 = hk * wi[0]; f0 = hk * wf[0]; g0 = hk * wg[0]; o0 = hk * wo[0];
        }
        {
            const float hk = __shfl_sync(0xffffffffu, h, 16);
            i1 = hk * wi[16]; f1 = hk * wf[16]; g1 = hk * wg[16]; o1 = hk * wo[16];
        }
        #pragma unroll
        for (int k = 1; k < 16; k++){
            const float ha = __shfl_sync(0xffffffffu, h, k);
            const float hb = __shfl_sync(0xffffffffu, h, k + 16);
            i0 = fmaf(ha, wi[k], i0);       i1 = fmaf(hb, wi[k + 16], i1);
            f0 = fmaf(ha, wf[k], f0);       f1 = fmaf(hb, wf[k + 16], f1);
            g0 = fmaf(ha, wg[k], g0);       g1 = fmaf(hb, wg[k + 16], g1);
            o0 = fmaf(ha, wo[k], o0);       o1 = fmaf(hb, wo[k + 16], o1);
        }

        const float gi = sigt((z4.x + i0) + i1);
        const float gf = sigt((z4.y + f0) + f1);
        const float gg = tanha((z4.z + g0) + g1);
        const float go = sigt((z4.w + o0) + o1);

        const float cn = fmaf(gf, c, gi * gg);
        const float hn = go * tanha(cn);
        const bool  m  = (tok != 0);
        c = m ? cn : c;
        h = m ? hn : h;

        optr[(size_t)t * HIDD] = h;          // coalesced 128B per warp
    }
}

extern "C" void kernel_launch(void* const* d_in, const int* in_sizes, int n_in,
                              void* d_out, int out_size)
{
    (void)in_sizes; (void)n_in; (void)out_size;
    const int*   tokens = (const int*)  d_in[0];
    const float* emb    = (const float*)d_in[1];
    const float* Wk     = (const float*)d_in[2];
    const float* Wr     = (const float*)d_in[3];
    const float* bias   = (const float*)d_in[4];
    float* out = (float*)d_out;

    proj_kernel<<<BATCH, 256>>>(tokens, emb, Wk, bias);
    rec_kernel<<<BATCH, 32>>>(tokens, Wr, out);
}

// round 7
// speedup vs baseline: 2.1358x; 1.1828x over previous
#include <cuda_runtime.h>

#define BATCH 256
#define SEQ   2048
#define EMBD  16
#define HIDD  32
#define GATE  128

typedef unsigned long long u64;

// 256 MB scratch: gate-packed input projection, float4(i,f,g,o) per (token, hid)
__device__ float4 g_zx[(size_t)BATCH * SEQ * HIDD];

__device__ __forceinline__ u64 pack2(float lo, float hi){
    u64 r; asm("mov.b64 %0, {%1,%2};" : "=l"(r) : "f"(lo), "f"(hi)); return r;
}
__device__ __forceinline__ void unpack2(u64 v, float& lo, float& hi){
    asm("mov.b64 {%0,%1}, %2;" : "=f"(lo), "=f"(hi) : "l"(v));
}
__device__ __forceinline__ u64 ffma2(u64 a, u64 b, u64 c){
    u64 d; asm("fma.rn.f32x2 %0, %1, %2, %3;" : "=l"(d) : "l"(a), "l"(b), "l"(c)); return d;
}
__device__ __forceinline__ float tanha(float x){
    float y; asm("tanh.approx.f32 %0, %1;" : "=f"(y) : "f"(x)); return y;
}
// sigmoid(z) = 0.5 + 0.5*tanh(z/2)
__device__ __forceinline__ float sigt(float z){
    return fmaf(0.5f, tanha(0.5f * z), 0.5f);
}

// ─────────────── Phase 1: zx = emb[tok]@Wk + b  (proven, ~90us) ─────────────
__global__ __launch_bounds__(256) void proj_kernel(
    const int*   __restrict__ tokens,
    const float* __restrict__ emb,
    const float* __restrict__ Wk,
    const float* __restrict__ bias)
{
    const int j    = threadIdx.x & 31;
    const int warp = (blockIdx.x << 3) + (threadIdx.x >> 5);
    const int base = warp << 8;

    u64 wk_if[EMBD], wk_go[EMBD];
    #pragma unroll
    for (int e = 0; e < EMBD; e++){
        wk_if[e] = pack2(Wk[e*GATE + j],      Wk[e*GATE + j + 32]);
        wk_go[e] = pack2(Wk[e*GATE + j + 64], Wk[e*GATE + j + 96]);
    }
    const u64 b_if = pack2(bias[j],      bias[j + 32]);
    const u64 b_go = pack2(bias[j + 64], bias[j + 96]);

    for (int s = 0; s < 256; s += 2){
        const int tflat = base + s + (j >> 4);
        const int tok   = tokens[tflat];
        const float xv  = emb[tok * EMBD + (j & 15)];

        u64 aI = b_if, aG = b_go;
        u64 cI = b_if, cG = b_go;
        #pragma unroll
        for (int e = 0; e < EMBD; e++){
            float xa = __shfl_sync(0xffffffffu, xv, e);
            float xb = __shfl_sync(0xffffffffu, xv, 16 + e);
            u64 xa2 = pack2(xa, xa);
            u64 xb2 = pack2(xb, xb);
            aI = ffma2(xa2, wk_if[e], aI);
            aG = ffma2(xa2, wk_go[e], aG);
            cI = ffma2(xb2, wk_if[e], cI);
            cG = ffma2(xb2, wk_go[e], cG);
        }
        float4 zA, zB;
        unpack2(aI, zA.x, zA.y); unpack2(aG, zA.z, zA.w);
        unpack2(cI, zB.x, zB.y); unpack2(cG, zB.z, zB.w);
        g_zx[(size_t)(base + s)     * HIDD + j] = zA;
        g_zx[(size_t)(base + s + 1) * HIDD + j] = zB;
    }
}

// ─────────────── Phase 2: single-warp recurrence, smem h-broadcast ──────────
// One warp per sequence. Lane j owns hid j + gate columns (j,j+32,j+64,j+96):
// gate combine is lane-local. h exchanged via double-buffered smem (STS.32 +
// one __syncwarp + 8 broadcast LDS.128) — measured cheaper than shfl (R6) and
// cross-warp bar (R5). 128 scalar FFMA/step (256cy issue floor) in 8 chains;
// 5 MUFU.TANH tail. Branch-free; unroll-4-matched register rings.
__global__ __launch_bounds__(32) void rec_kernel(
    const int*   __restrict__ tokens,
    const float* __restrict__ Wr,
    float*       __restrict__ out)
{
    __shared__ float hs[2][HIDD];

    const int b = blockIdx.x;
    const int j = threadIdx.x;

    float wi[HIDD], wf[HIDD], wg[HIDD], wo[HIDD];
    #pragma unroll
    for (int k = 0; k < HIDD; k++){
        wi[k] = Wr[k*GATE + j];
        wf[k] = Wr[k*GATE + j + 32];
        wg[k] = Wr[k*GATE + j + 64];
        wo[k] = Wr[k*GATE + j + 96];
    }

    const float4* __restrict__ zp   = g_zx + (size_t)b * SEQ * HIDD + j;
    const int*    __restrict__ tptr = tokens + b * SEQ;
    float* optr = out + (size_t)b * SEQ * HIDD + j;

    float4 rz[4]; int rtok[4];
    #pragma unroll
    for (int p = 0; p < 3; p++){
        rz[p]   = zp[(size_t)p * HIDD];
        rtok[p] = tptr[p];
    }

    hs[0][j] = 0.0f;
    __syncwarp();

    float h = 0.0f, c = 0.0f;

    #pragma unroll 4
    for (int t = 0; t < SEQ; t++){
        const int rb = t & 1, wb = rb ^ 1;

        // prefetch t+3 (clamped; ring indices compile-time under unroll 4)
        const int pidx = min(t + 3, SEQ - 1);
        rz[(t + 3) & 3]   = zp[(size_t)pidx * HIDD];
        rtok[(t + 3) & 3] = tptr[pidx];

        const float4 z4  = rz[t & 3];
        const int    tok = rtok[t & 3];

        // z = zx + Wr^T h : 8 chains (2 per gate), h via broadcast LDS.128
        const float4* hb = (const float4*)hs[rb];
        float i0, i1, f0, f1, g0, g1, o0, o1;
        {
            const float4 h0 = hb[0], h1 = hb[1], h2 = hb[2], h3 = hb[3];
            i0 = fmaf(h0.x, wi[0], z4.x); f0 = fmaf(h0.x, wf[0], z4.y);
            g0 = fmaf(h0.x, wg[0], z4.z); o0 = fmaf(h0.x, wo[0], z4.w);
            i0 = fmaf(h0.y, wi[1], i0);   f0 = fmaf(h0.y, wf[1], f0);
            g0 = fmaf(h0.y, wg[1], g0);   o0 = fmaf(h0.y, wo[1], o0);
            i0 = fmaf(h0.z, wi[2], i0);   f0 = fmaf(h0.z, wf[2], f0);
            g0 = fmaf(h0.z, wg[2], g0);   o0 = fmaf(h0.z, wo[2], o0);
            i0 = fmaf(h0.w, wi[3], i0);   f0 = fmaf(h0.w, wf[3], f0);
            g0 = fmaf(h0.w, wg[3], g0);   o0 = fmaf(h0.w, wo[3], o0);
            i0 = fmaf(h1.x, wi[4], i0);   f0 = fmaf(h1.x, wf[4], f0);
            g0 = fmaf(h1.x, wg[4], g0);   o0 = fmaf(h1.x, wo[4], o0);
            i0 = fmaf(h1.y, wi[5], i0);   f0 = fmaf(h1.y, wf[5], f0);
            g0 = fmaf(h1.y, wg[5], g0);   o0 = fmaf(h1.y, wo[5], o0);
            i0 = fmaf(h1.z, wi[6], i0);   f0 = fmaf(h1.z, wf[6], f0);
            g0 = fmaf(h1.z, wg[6], g0);   o0 = fmaf(h1.z, wo[6], o0);
            i0 = fmaf(h1.w, wi[7], i0);   f0 = fmaf(h1.w, wf[7], f0);
            g0 = fmaf(h1.w, wg[7], g0);   o0 = fmaf(h1.w, wo[7], o0);
            i0 = fmaf(h2.x, wi[8], i0);   f0 = fmaf(h2.x, wf[8], f0);
            g0 = fmaf(h2.x, wg[8], g0);   o0 = fmaf(h2.x, wo[8], o0);
            i0 = fmaf(h2.y, wi[9], i0);   f0 = fmaf(h2.y, wf[9], f0);
            g0 = fmaf(h2.y, wg[9], g0);   o0 = fmaf(h2.y, wo[9], o0);
            i0 = fmaf(h2.z, wi[10], i0);  f0 = fmaf(h2.z, wf[10], f0);
            g0 = fmaf(h2.z, wg[10], g0);  o0 = fmaf(h2.z, wo[10], o0);
            i0 = fmaf(h2.w, wi[11], i0);  f0 = fmaf(h2.w, wf[11], f0);
            g0 = fmaf(h2.w, wg[11], g0);  o0 = fmaf(h2.w, wo[11], o0);
            i0 = fmaf(h3.x, wi[12], i0);  f0 = fmaf(h3.x, wf[12], f0);
            g0 = fmaf(h3.x, wg[12], g0);  o0 = fmaf(h3.x, wo[12], o0);
            i0 = fmaf(h3.y, wi[13], i0);  f0 = fmaf(h3.y, wf[13], f0);
            g0 = fmaf(h3.y, wg[13], g0);  o0 = fmaf(h3.y, wo[13], o0);
            i0 = fmaf(h3.z, wi[14], i0);  f0 = fmaf(h3.z, wf[14], f0);
            g0 = fmaf(h3.z, wg[14], g0);  o0 = fmaf(h3.z, wo[14], o0);
            i0 = fmaf(h3.w, wi[15], i0);  f0 = fmaf(h3.w, wf[15], f0);
            g0 = fmaf(h3.w, wg[15], g0);  o0 = fmaf(h3.w, wo[15], o0);
        }
        {
            const float4 h4 = hb[4], h5 = hb[5], h6 = hb[6], h7 = hb[7];
            i1 = h4.x * wi[16];           f1 = h4.x * wf[16];
            g1 = h4.x * wg[16];           o1 = h4.x * wo[16];
            i1 = fmaf(h4.y, wi[17], i1);  f1 = fmaf(h4.y, wf[17], f1);
            g1 = fmaf(h4.y, wg[17], g1);  o1 = fmaf(h4.y, wo[17], o1);
            i1 = fmaf(h4.z, wi[18], i1);  f1 = fmaf(h4.z, wf[18], f1);
            g1 = fmaf(h4.z, wg[18], g1);  o1 = fmaf(h4.z, wo[18], o1);
            i1 = fmaf(h4.w, wi[19], i1);  f1 = fmaf(h4.w, wf[19], f1);
            g1 = fmaf(h4.w, wg[19], g1);  o1 = fmaf(h4.w, wo[19], o1);
            i1 = fmaf(h5.x, wi[20], i1);  f1 = fmaf(h5.x, wf[20], f1);
            g1 = fmaf(h5.x, wg[20], g1);  o1 = fmaf(h5.x, wo[20], o1);
            i1 = fmaf(h5.y, wi[21], i1);  f1 = fmaf(h5.y, wf[21], f1);
            g1 = fmaf(h5.y, wg[21], g1);  o1 = fmaf(h5.y, wo[21], o1);
            i1 = fmaf(h5.z, wi[22], i1);  f1 = fmaf(h5.z, wf[22], f1);
            g1 = fmaf(h5.z, wg[22], g1);  o1 = fmaf(h5.z, wo[22], o1);
            i1 = fmaf(h5.w, wi[23], i1);  f1 = fmaf(h5.w, wf[23], f1);
            g1 = fmaf(h5.w, wg[23], g1);  o1 = fmaf(h5.w, wo[23], o1);
            i1 = fmaf(h6.x, wi[24], i1);  f1 = fmaf(h6.x, wf[24], f1);
            g1 = fmaf(h6.x, wg[24], g1);  o1 = fmaf(h6.x, wo[24], o1);
            i1 = fmaf(h6.y, wi[25], i1);  f1 = fmaf(h6.y, wf[25], f1);
            g1 = fmaf(h6.y, wg[25], g1);  o1 = fmaf(h6.y, wo[25], o1);
            i1 = fmaf(h6.z, wi[26], i1);  f1 = fmaf(h6.z, wf[26], f1);
            g1 = fmaf(h6.z, wg[26], g1);  o1 = fmaf(h6.z, wo[26], o1);
            i1 = fmaf(h6.w, wi[27], i1);  f1 = fmaf(h6.w, wf[27], f1);
            g1 = fmaf(h6.w, wg[27], g1);  o1 = fmaf(h6.w, wo[27], o1);
            i1 = fmaf(h7.x, wi[28], i1);  f1 = fmaf(h7.x, wf[28], f1);
            g1 = fmaf(h7.x, wg[28], g1);  o1 = fmaf(h7.x, wo[28], o1);
            i1 = fmaf(h7.y, wi[29], i1);  f1 = fmaf(h7.y, wf[29], f1);
            g1 = fmaf(h7.y, wg[29], g1);  o1 = fmaf(h7.y, wo[29], o1);
            i1 = fmaf(h7.z, wi[30], i1);  f1 = fmaf(h7.z, wf[30], f1);
            g1 = fmaf(h7.z, wg[30], g1);  o1 = fmaf(h7.z, wo[30], o1);
            i1 = fmaf(h7.w, wi[31], i1);  f1 = fmaf(h7.w, wf[31], f1);
            g1 = fmaf(h7.w, wg[31], g1);  o1 = fmaf(h7.w, wo[31], o1);
        }

        const float gi = sigt(i0 + i1);
        const float gf = sigt(f0 + f1);
        const float gg = tanha(g0 + g1);
        const float go = sigt(o0 + o1);

        const float cn = fmaf(gf, c, gi * gg);
        const float hn = go * tanha(cn);
        const bool  m  = (tok != 0);
        c = m ? cn : c;
        h = m ? hn : h;

        hs[wb][j] = h;
        optr[(size_t)t * HIDD] = h;          // coalesced 128B per warp
        __syncwarp();
    }
}

extern "C" void kernel_launch(void* const* d_in, const int* in_sizes, int n_in,
                              void* d_out, int out_size)
{
    (void)in_sizes; (void)n_in; (void)out_size;
    const int*   tokens = (const int*)  d_in[0];
    const float* emb    = (const float*)d_in[1];
    const float* Wk     = (const float*)d_in[2];
    const float* Wr     = (const float*)d_in[3];
    const float* bias   = (const float*)d_in[4];
    float* out = (float*)d_out;

    proj_kernel<<<BATCH, 256>>>(tokens, emb, Wk, bias);
    rec_kernel<<<BATCH, 32>>>(tokens, Wr, out);
}